// round 1
// baseline (speedup 1.0000x reference)
#include <cuda_runtime.h>
#include <cstdint>

#define BH    64
#define T_LEN 4096
#define D_DIM 128
#define SPLIT 16
#define CHUNK (T_LEN / SPLIT)   // 256
#define TS    32

// Scratch: partial KV per split, then reduced KV. Static device arrays (no allocs).
__device__ float g_kvp[SPLIT * BH * D_DIM * D_DIM];  // 67 MB
__device__ float g_kv [BH * D_DIM * D_DIM];          // 4 MB

// ---- packed f32x2 helpers (Blackwell FFMA2 via PTX) ----
__device__ __forceinline__ unsigned long long pack_dup(float x) {
    unsigned long long r;
    unsigned int xi = __float_as_uint(x);
    asm("mov.b64 %0, {%1, %1};" : "=l"(r) : "r"(xi));
    return r;
}
__device__ __forceinline__ void ffma2(unsigned long long& d,
                                      unsigned long long a,
                                      unsigned long long b) {
    asm("fma.rn.f32x2 %0, %1, %2, %3;" : "=l"(d) : "l"(a), "l"(b), "l"(d));
}

// ============================================================================
// Kernel 1: partial KV^T accumulation.
// grid = (SPLIT, BH), block = 256 (16x16 thread tile, 8x8 outputs/thread).
// C[d][e] += sum_t K[t][d] * V[t][e] over this CTA's 256-row T chunk.
// ============================================================================
__global__ __launch_bounds__(256) void kv_partial(const float* __restrict__ K,
                                                  const float* __restrict__ V) {
    __shared__ float Ks[TS][D_DIM];   // 16 KB
    __shared__ float Vs[TS][D_DIM];   // 16 KB

    const int bh = blockIdx.y;
    const int t0 = blockIdx.x * CHUNK;
    const float* Kb = K + (size_t)bh * T_LEN * D_DIM;
    const float* Vb = V + (size_t)bh * T_LEN * D_DIM;

    const int tid = threadIdx.x;
    const int tx = tid & 15;          // output cols (e):  tx*8 .. tx*8+7
    const int ty = tid >> 4;          // output rows (d):  ty*8 .. ty*8+7

    unsigned long long acc[8][4];     // 8 rows x 4 packed-pairs (= 8 cols)
    #pragma unroll
    for (int i = 0; i < 8; i++)
        #pragma unroll
        for (int j = 0; j < 4; j++) acc[i][j] = 0ULL;

    for (int tt = 0; tt < CHUNK; tt += TS) {
        const float4* Kg = (const float4*)(Kb + (size_t)(t0 + tt) * D_DIM);
        const float4* Vg = (const float4*)(Vb + (size_t)(t0 + tt) * D_DIM);
        float4* Ks4 = (float4*)Ks;
        float4* Vs4 = (float4*)Vs;
        #pragma unroll
        for (int i = 0; i < 4; i++) {          // 32*128 floats = 1024 float4
            int lin = tid + 256 * i;
            Ks4[lin] = Kg[lin];
            Vs4[lin] = Vg[lin];
        }
        __syncthreads();

        #pragma unroll 8
        for (int t = 0; t < TS; t++) {
            float4 k0 = *(const float4*)&Ks[t][ty * 8];
            float4 k1 = *(const float4*)&Ks[t][ty * 8 + 4];
            unsigned long long a[8];
            a[0] = pack_dup(k0.x); a[1] = pack_dup(k0.y);
            a[2] = pack_dup(k0.z); a[3] = pack_dup(k0.w);
            a[4] = pack_dup(k1.x); a[5] = pack_dup(k1.y);
            a[6] = pack_dup(k1.z); a[7] = pack_dup(k1.w);

            const ulonglong2* vrow = (const ulonglong2*)&Vs[t][tx * 8];
            ulonglong2 v0 = vrow[0];
            ulonglong2 v1 = vrow[1];
            unsigned long long b[4] = {v0.x, v0.y, v1.x, v1.y};

            #pragma unroll
            for (int i = 0; i < 8; i++)
                #pragma unroll
                for (int j = 0; j < 4; j++) ffma2(acc[i][j], a[i], b[j]);
        }
        __syncthreads();
    }

    float* gp = g_kvp + ((size_t)blockIdx.x * BH + bh) * D_DIM * D_DIM;
    #pragma unroll
    for (int i = 0; i < 8; i++) {
        ulonglong2* orow = (ulonglong2*)&gp[(ty * 8 + i) * D_DIM + tx * 8];
        orow[0] = make_ulonglong2(acc[i][0], acc[i][1]);
        orow[1] = make_ulonglong2(acc[i][2], acc[i][3]);
    }
}

// ============================================================================
// Kernel 2: reduce SPLIT partials into g_kv. 262144 float4 total.
// grid = 1024, block = 256.
// ============================================================================
__global__ __launch_bounds__(256) void kv_reduce() {
    const int idx = blockIdx.x * 256 + threadIdx.x;     // float4 index
    const float4* p4 = (const float4*)g_kvp;
    float4 s = p4[idx];
    #pragma unroll
    for (int p = 1; p < SPLIT; p++) {
        float4 v = p4[(size_t)p * (BH * D_DIM * D_DIM / 4) + idx];
        s.x += v.x; s.y += v.y; s.z += v.z; s.w += v.w;
    }
    ((float4*)g_kv)[idx] = s;
}

// ============================================================================
// Kernel 3: out = Q @ KV.
// grid = (T/128, BH), block = 256 (16x16 threads, 8x8 outputs each).
// Dynamic smem: KVs[128][128] (64 KB) + Qs[128][32] (16 KB) = 80 KB.
// ============================================================================
__global__ __launch_bounds__(256) void out_kernel(const float* __restrict__ Q,
                                                  float* __restrict__ out) {
    extern __shared__ float sm[];
    float* KVs = sm;            // 16384 floats, row-major [d][e]
    float* Qs  = sm + 16384;    // 128 rows x 32 d-cols

    const int bh = blockIdx.y;
    const int trow0 = blockIdx.x * 128;
    const float* Qb = Q + (size_t)bh * T_LEN * D_DIM + (size_t)trow0 * D_DIM;
    float* Ob = out + (size_t)bh * T_LEN * D_DIM + (size_t)trow0 * D_DIM;

    const int tid = threadIdx.x;
    const int tx = tid & 15;    // output cols (e)
    const int ty = tid >> 4;    // output rows (t)

    // Load the full KV tile for this bh (4096 float4, 16 per thread).
    {
        const float4* kv4 = (const float4*)(g_kv + (size_t)bh * D_DIM * D_DIM);
        float4* s4 = (float4*)KVs;
        #pragma unroll
        for (int i = 0; i < 16; i++) s4[tid + 256 * i] = kv4[tid + 256 * i];
    }

    unsigned long long acc[8][4];
    #pragma unroll
    for (int i = 0; i < 8; i++)
        #pragma unroll
        for (int j = 0; j < 4; j++) acc[i][j] = 0ULL;

    for (int d0 = 0; d0 < D_DIM; d0 += 32) {
        // Load Q tile [128 t][32 d]: 1024 float4, 4 per thread.
        const float4* Qg4 = (const float4*)Qb;
        float4* Qs4 = (float4*)Qs;
        #pragma unroll
        for (int i = 0; i < 4; i++) {
            int lin = tid + 256 * i;           // 0..1023
            int row = lin >> 3;                // t row (8 float4 per row)
            int c4  = lin & 7;                 // float4 within 32-d slice
            Qs4[lin] = Qg4[row * 32 + (d0 >> 2) + c4];
        }
        __syncthreads();

        #pragma unroll 4
        for (int d = 0; d < 32; d++) {
            const ulonglong2* kvrow =
                (const ulonglong2*)&KVs[(d0 + d) * D_DIM + tx * 8];
            ulonglong2 b0 = kvrow[0];
            ulonglong2 b1 = kvrow[1];
            unsigned long long b[4] = {b0.x, b0.y, b1.x, b1.y};

            #pragma unroll
            for (int i = 0; i < 8; i++) {
                unsigned long long a = pack_dup(Qs[(ty * 8 + i) * 32 + d]);
                #pragma unroll
                for (int j = 0; j < 4; j++) ffma2(acc[i][j], a, b[j]);
            }
        }
        __syncthreads();
    }

    #pragma unroll
    for (int i = 0; i < 8; i++) {
        ulonglong2* orow = (ulonglong2*)&Ob[(ty * 8 + i) * D_DIM + tx * 8];
        orow[0] = make_ulonglong2(acc[i][0], acc[i][1]);
        orow[1] = make_ulonglong2(acc[i][2], acc[i][3]);
    }
}

// ============================================================================
extern "C" void kernel_launch(void* const* d_in, const int* in_sizes, int n_in,
                              void* d_out, int out_size) {
    const float* Q = (const float*)d_in[0];
    const float* K = (const float*)d_in[1];
    const float* V = (const float*)d_in[2];
    float* out = (float*)d_out;

    kv_partial<<<dim3(SPLIT, BH), 256>>>(K, V);
    kv_reduce<<<1024, 256>>>();

    const int smem2 = (16384 + 4096) * sizeof(float);   // 80 KB
    cudaFuncSetAttribute(out_kernel,
                         cudaFuncAttributeMaxDynamicSharedMemorySize, smem2);
    out_kernel<<<dim3(T_LEN / 128, BH), 256, smem2>>>(Q, out);
}

// round 3
// speedup vs baseline: 1.6028x; 1.6028x over previous
#include <cuda_runtime.h>
#include <cuda_fp16.h>
#include <cstdint>

#define BH    64
#define T_LEN 4096
#define D_DIM 128
#define SPLIT 16
#define CHUNK (T_LEN / SPLIT)   // 256
#define TS    32
#define PAD   136               // 128 + 8 halves: conflict-free fragment loads

// Scratch (static device arrays — no allocs).
__device__ float g_kvp[SPLIT * BH * D_DIM * D_DIM];   // 67 MB fp32 KV^T partials
__device__ uint4 g_kvh4[BH * D_DIM * D_DIM / 8];      // 2 MB fp16 KV^T

// ---- packed f32x2 helpers (Blackwell FFMA2 via PTX) ----
__device__ __forceinline__ unsigned long long pack_dup(float x) {
    unsigned long long r;
    unsigned int xi = __float_as_uint(x);
    asm("mov.b64 %0, {%1, %1};" : "=l"(r) : "r"(xi));
    return r;
}
__device__ __forceinline__ void ffma2(unsigned long long& d,
                                      unsigned long long a,
                                      unsigned long long b) {
    asm("fma.rn.f32x2 %0, %1, %2, %3;" : "=l"(d) : "l"(a), "l"(b), "l"(d));
}

// ---- portable tensor-core mma (HMMA m16n8k16, fp16 in / fp32 acc) ----
__device__ __forceinline__ void mma16816(float* c, const uint32_t* a,
                                         const uint32_t* b) {
    asm volatile(
        "mma.sync.aligned.m16n8k16.row.col.f32.f16.f16.f32 "
        "{%0,%1,%2,%3}, {%4,%5,%6,%7}, {%8,%9}, {%0,%1,%2,%3};"
        : "+f"(c[0]), "+f"(c[1]), "+f"(c[2]), "+f"(c[3])
        : "r"(a[0]), "r"(a[1]), "r"(a[2]), "r"(a[3]), "r"(b[0]), "r"(b[1]));
}

// ============================================================================
// Kernel 1: partial KV^T accumulation (FFMA2, fp32).
// Called with (V, K):  C[e][d] += sum_t V[t][e] * K[t][d]  = KV^T.
// grid = (SPLIT, BH), block = 256 (16x16 thread tile, 8x8 outputs/thread).
// ============================================================================
__global__ __launch_bounds__(256) void kv_partial(const float* __restrict__ K,
                                                  const float* __restrict__ V) {
    __shared__ float Ks[TS][D_DIM];
    __shared__ float Vs[TS][D_DIM];

    const int bh = blockIdx.y;
    const int t0 = blockIdx.x * CHUNK;
    const float* Kb = K + (size_t)bh * T_LEN * D_DIM;
    const float* Vb = V + (size_t)bh * T_LEN * D_DIM;

    const int tid = threadIdx.x;
    const int tx = tid & 15;
    const int ty = tid >> 4;

    unsigned long long acc[8][4];
    #pragma unroll
    for (int i = 0; i < 8; i++)
        #pragma unroll
        for (int j = 0; j < 4; j++) acc[i][j] = 0ULL;

    for (int tt = 0; tt < CHUNK; tt += TS) {
        const float4* Kg = (const float4*)(Kb + (size_t)(t0 + tt) * D_DIM);
        const float4* Vg = (const float4*)(Vb + (size_t)(t0 + tt) * D_DIM);
        float4* Ks4 = (float4*)Ks;
        float4* Vs4 = (float4*)Vs;
        #pragma unroll
        for (int i = 0; i < 4; i++) {
            int lin = tid + 256 * i;
            Ks4[lin] = Kg[lin];
            Vs4[lin] = Vg[lin];
        }
        __syncthreads();

        #pragma unroll 8
        for (int t = 0; t < TS; t++) {
            float4 k0 = *(const float4*)&Ks[t][ty * 8];
            float4 k1 = *(const float4*)&Ks[t][ty * 8 + 4];
            unsigned long long a[8];
            a[0] = pack_dup(k0.x); a[1] = pack_dup(k0.y);
            a[2] = pack_dup(k0.z); a[3] = pack_dup(k0.w);
            a[4] = pack_dup(k1.x); a[5] = pack_dup(k1.y);
            a[6] = pack_dup(k1.z); a[7] = pack_dup(k1.w);

            const ulonglong2* vrow = (const ulonglong2*)&Vs[t][tx * 8];
            ulonglong2 v0 = vrow[0];
            ulonglong2 v1 = vrow[1];
            unsigned long long b[4] = {v0.x, v0.y, v1.x, v1.y};

            #pragma unroll
            for (int i = 0; i < 8; i++)
                #pragma unroll
                for (int j = 0; j < 4; j++) ffma2(acc[i][j], a[i], b[j]);
        }
        __syncthreads();
    }

    float* gp = g_kvp + ((size_t)blockIdx.x * BH + bh) * D_DIM * D_DIM;
    #pragma unroll
    for (int i = 0; i < 8; i++) {
        ulonglong2* orow = (ulonglong2*)&gp[(ty * 8 + i) * D_DIM + tx * 8];
        orow[0] = make_ulonglong2(acc[i][0], acc[i][1]);
        orow[1] = make_ulonglong2(acc[i][2], acc[i][3]);
    }
}

// ============================================================================
// Kernel 2: reduce SPLIT partials -> fp16 KV^T. grid=1024, block=256.
// ============================================================================
__global__ __launch_bounds__(256) void kv_reduce_h() {
    const int idx = blockIdx.x * 256 + threadIdx.x;     // float4 index (262144)
    const float4* p4 = (const float4*)g_kvp;
    float4 s = p4[idx];
    #pragma unroll
    for (int p = 1; p < SPLIT; p++) {
        float4 v = p4[(size_t)p * (BH * D_DIM * D_DIM / 4) + idx];
        s.x += v.x; s.y += v.y; s.z += v.z; s.w += v.w;
    }
    __half2 h0 = __floats2half2_rn(s.x, s.y);
    __half2 h1 = __floats2half2_rn(s.z, s.w);
    uint2 u;
    u.x = *reinterpret_cast<unsigned int*>(&h0);
    u.y = *reinterpret_cast<unsigned int*>(&h1);
    ((uint2*)g_kvh4)[idx] = u;
}

// ============================================================================
// Kernel 3: out = Q @ KV via mma.sync m16n8k16 (HMMA).
// grid = (32 t-tiles, 64 bh), block = 256 (8 warps: 4m x 2n, warp tile 32x64).
// A = Qs[128][PAD] fp16 row-major (t x d); B = Ws[128][PAD] = KV^T (e x d),
// which is exactly the col-major k x n operand of mma .row.col.
// ============================================================================
__global__ __launch_bounds__(256, 2) void out_hmma(const float* __restrict__ Q,
                                                   float* __restrict__ out) {
    extern __shared__ __half sm[];
    __half* Qs = sm;                 // [128][PAD]
    __half* Ws = sm + 128 * PAD;     // [128][PAD]

    const int tid = threadIdx.x;
    const int bh = blockIdx.y;
    const int t0 = blockIdx.x * 128;

    // ---- load + convert Q tile (fp32 -> fp16) ----
    {
        const float4* Qg4 = (const float4*)(Q + ((size_t)bh * T_LEN + t0) * D_DIM);
        #pragma unroll
        for (int u = 0; u < 8; u++) {
            int idx = tid + 256 * u;      // 2048 uint4 units
            int row = idx >> 4;           // t row 0..127
            int c8  = idx & 15;           // 8-half group along d
            float4 fa = Qg4[row * 32 + c8 * 2];
            float4 fb = Qg4[row * 32 + c8 * 2 + 1];
            __half2 h0 = __floats2half2_rn(fa.x, fa.y);
            __half2 h1 = __floats2half2_rn(fa.z, fa.w);
            __half2 h2 = __floats2half2_rn(fb.x, fb.y);
            __half2 h3 = __floats2half2_rn(fb.z, fb.w);
            uint4 pk;
            pk.x = *reinterpret_cast<unsigned int*>(&h0);
            pk.y = *reinterpret_cast<unsigned int*>(&h1);
            pk.z = *reinterpret_cast<unsigned int*>(&h2);
            pk.w = *reinterpret_cast<unsigned int*>(&h3);
            *(uint4*)&Qs[row * PAD + c8 * 8] = pk;
        }
    }
    // ---- load fp16 KV^T tile ----
    {
        const uint4* Bg = g_kvh4 + (size_t)bh * 2048;
        #pragma unroll
        for (int u = 0; u < 8; u++) {
            int idx = tid + 256 * u;
            int row = idx >> 4;           // e row 0..127
            int c8  = idx & 15;
            *(uint4*)&Ws[row * PAD + c8 * 8] = Bg[row * 16 + c8];
        }
    }
    __syncthreads();

    const int wid = tid >> 5;
    const int l   = tid & 31;
    const int g   = l >> 2;            // group id 0..7
    const int q2  = (l & 3) * 2;       // quad col pair
    const int wm  = (wid & 3) * 32;    // warp m origin
    const int wn  = (wid >> 2) * 64;   // warp n origin

    float acc[2][8][4];
    #pragma unroll
    for (int i = 0; i < 2; i++)
        #pragma unroll
        for (int j = 0; j < 8; j++)
            #pragma unroll
            for (int v = 0; v < 4; v++) acc[i][j][v] = 0.f;

    #pragma unroll
    for (int k0 = 0; k0 < 128; k0 += 16) {
        uint32_t af[2][4];
        #pragma unroll
        for (int mi = 0; mi < 2; mi++) {
            int r = wm + mi * 16 + g;
            af[mi][0] = *(const uint32_t*)&Qs[r * PAD + k0 + q2];
            af[mi][1] = *(const uint32_t*)&Qs[(r + 8) * PAD + k0 + q2];
            af[mi][2] = *(const uint32_t*)&Qs[r * PAD + k0 + q2 + 8];
            af[mi][3] = *(const uint32_t*)&Qs[(r + 8) * PAD + k0 + q2 + 8];
        }
        #pragma unroll
        for (int ni = 0; ni < 8; ni++) {
            int e = wn + ni * 8 + g;
            uint32_t bf[2];
            bf[0] = *(const uint32_t*)&Ws[e * PAD + k0 + q2];
            bf[1] = *(const uint32_t*)&Ws[e * PAD + k0 + q2 + 8];
            mma16816(acc[0][ni], af[0], bf);
            mma16816(acc[1][ni], af[1], bf);
        }
    }

    // ---- epilogue: direct fp32 stores ----
    float* Ob = out + ((size_t)bh * T_LEN + t0) * D_DIM;
    #pragma unroll
    for (int mi = 0; mi < 2; mi++) {
        #pragma unroll
        for (int ni = 0; ni < 8; ni++) {
            int r = wm + mi * 16 + g;
            int c = wn + ni * 8 + q2;
            *(float2*)&Ob[(size_t)r * D_DIM + c] =
                make_float2(acc[mi][ni][0], acc[mi][ni][1]);
            *(float2*)&Ob[(size_t)(r + 8) * D_DIM + c] =
                make_float2(acc[mi][ni][2], acc[mi][ni][3]);
        }
    }
}

// ============================================================================
extern "C" void kernel_launch(void* const* d_in, const int* in_sizes, int n_in,
                              void* d_out, int out_size) {
    const float* Q = (const float*)d_in[0];
    const float* K = (const float*)d_in[1];
    const float* V = (const float*)d_in[2];
    float* out = (float*)d_out;

    // KV^T partials: call with (V, K) so C[e][d] = sum_t V[t][e] K[t][d].
    kv_partial<<<dim3(SPLIT, BH), 256>>>(V, K);
    kv_reduce_h<<<1024, 256>>>();

    const int smem = 2 * 128 * PAD * sizeof(__half);   // 69632 B
    cudaFuncSetAttribute(out_hmma,
                         cudaFuncAttributeMaxDynamicSharedMemorySize, smem);
    out_hmma<<<dim3(T_LEN / 128, BH), 256, smem>>>(Q, out);
}

// round 7
// speedup vs baseline: 3.3750x; 2.1057x over previous
#include <cuda_runtime.h>
#include <cuda_fp16.h>
#include <cstdint>

#define BH    64
#define T_LEN 4096
#define D_DIM 128
#define SPLIT 8
#define CHUNK (T_LEN / SPLIT)   // 512
#define KSLAB 32
#define ASTR  136               // smem row stride in halves (16B-aligned rows)
#define PAD   136               // phase-B smem pad

// Scratch (static device arrays — no allocs).
__device__ float g_kvp[SPLIT * BH * D_DIM * D_DIM];   // 33.5 MB fp32 KV^T partials
__device__ uint4 g_kvh4[BH * D_DIM * D_DIM / 8];      // 2 MB fp16 KV^T

// ---- portable tensor-core mma (HMMA m16n8k16, fp16 in / fp32 acc) ----
__device__ __forceinline__ void mma16816(float* c, const uint32_t* a,
                                         const uint32_t* b) {
    asm volatile(
        "mma.sync.aligned.m16n8k16.row.col.f32.f16.f16.f32 "
        "{%0,%1,%2,%3}, {%4,%5,%6,%7}, {%8,%9}, {%0,%1,%2,%3};"
        : "+f"(c[0]), "+f"(c[1]), "+f"(c[2]), "+f"(c[3])
        : "r"(a[0]), "r"(a[1]), "r"(a[2]), "r"(a[3]), "r"(b[0]), "r"(b[1]));
}
__device__ __forceinline__ void ldsm_x4_t(uint32_t* r, uint32_t addr) {
    asm volatile(
        "ldmatrix.sync.aligned.m8n8.x4.trans.shared.b16 {%0,%1,%2,%3}, [%4];"
        : "=r"(r[0]), "=r"(r[1]), "=r"(r[2]), "=r"(r[3]) : "r"(addr));
}
__device__ __forceinline__ uint32_t smem_u32(const void* p) {
    uint32_t a;
    asm("{ .reg .u64 t; cvta.to.shared.u64 t, %1; cvt.u32.u64 %0, t; }"
        : "=r"(a) : "l"(p));
    return a;
}
__device__ __forceinline__ uint2 cvt4h(float4 f) {
    __half2 h0 = __floats2half2_rn(f.x, f.y);
    __half2 h1 = __floats2half2_rn(f.z, f.w);
    uint2 u;
    u.x = *reinterpret_cast<unsigned int*>(&h0);
    u.y = *reinterpret_cast<unsigned int*>(&h1);
    return u;
}

// ============================================================================
// Kernel 1: KV^T partials via HMMA.
// C[e][d] = sum_t V[t][e] * K[t][d] over a 512-t chunk. M=e=128, N=d=128.
// Smem holds K,V slabs naturally [t][*] fp16; transposed fragments come from
// ldmatrix.x4.trans. grid = (SPLIT, BH), block = 256 (8 warps, 4m x 2n).
// ============================================================================
__global__ __launch_bounds__(256) void kv_hmma(const float* __restrict__ K,
                                               const float* __restrict__ V) {
    __shared__ __half Ks[KSLAB * ASTR];   // [t][d]
    __shared__ __half Vs[KSLAB * ASTR];   // [t][e]

    const int tid = threadIdx.x;
    const int bh = blockIdx.y;
    const int t0c = blockIdx.x * CHUNK;
    const float4* Kg4 = (const float4*)(K + (size_t)bh * T_LEN * D_DIM);
    const float4* Vg4 = (const float4*)(V + (size_t)bh * T_LEN * D_DIM);

    const int wid = tid >> 5;
    const int l   = tid & 31;
    const int g   = l >> 2;
    const int q2  = (l & 3) * 2;
    const int wm  = (wid & 3) * 32;     // e origin
    const int wn  = (wid >> 2) * 64;    // d origin

    const uint32_t ks_base = smem_u32(Ks);
    const uint32_t vs_base = smem_u32(Vs);
    // ldmatrix.trans per-lane addresses (derived from validated R3 layout):
    // A (from Vs): row = (l&7) + 8*(l>>4), col = 8*((l>>3)&1)
    // B (from Ks): row = (l&7) + 8*((l>>3)&1), col = 8*(l>>4)
    const int a_row = (l & 7) + 8 * (l >> 4);
    const int a_col = wm + 8 * ((l >> 3) & 1);
    const int b_row = (l & 7) + 8 * ((l >> 3) & 1);
    const int b_col = wn + 8 * (l >> 4);

    float acc[2][8][4];
    #pragma unroll
    for (int i = 0; i < 2; i++)
        #pragma unroll
        for (int j = 0; j < 8; j++)
            #pragma unroll
            for (int v = 0; v < 4; v++) acc[i][j][v] = 0.f;

    // stage registers: 4 float4 each for K and V (slab = 32t x 32 float4)
    float4 sk[4], sv[4];
    #pragma unroll
    for (int i = 0; i < 4; i++) {
        int lin = tid + 256 * i;
        int t = lin >> 5, e4 = lin & 31;
        sk[i] = Kg4[(size_t)(t0c + t) * 32 + e4];
        sv[i] = Vg4[(size_t)(t0c + t) * 32 + e4];
    }

    for (int s = 0; s < CHUNK / KSLAB; s++) {
        // convert + store staged slab to smem (natural layout, coalesced)
        #pragma unroll
        for (int i = 0; i < 4; i++) {
            int lin = tid + 256 * i;
            int t = lin >> 5, e4 = lin & 31;
            *(uint2*)&Ks[t * ASTR + e4 * 4] = cvt4h(sk[i]);
            *(uint2*)&Vs[t * ASTR + e4 * 4] = cvt4h(sv[i]);
        }
        __syncthreads();

        // prefetch next slab while MMAs run
        if (s + 1 < CHUNK / KSLAB) {
            #pragma unroll
            for (int i = 0; i < 4; i++) {
                int lin = tid + 256 * i;
                int t = lin >> 5, e4 = lin & 31;
                sk[i] = Kg4[(size_t)(t0c + (s + 1) * KSLAB + t) * 32 + e4];
                sv[i] = Vg4[(size_t)(t0c + (s + 1) * KSLAB + t) * 32 + e4];
            }
        }

        #pragma unroll
        for (int k0 = 0; k0 < KSLAB; k0 += 16) {
            // A fragments: 2 m-tiles (e = wm, wm+16)
            uint32_t af[2][4];
            #pragma unroll
            for (int mi = 0; mi < 2; mi++)
                ldsm_x4_t(af[mi],
                          vs_base + ((k0 + a_row) * ASTR + a_col + 16 * mi) * 2);
            // B fragments: 4 x4-loads cover 8 n-tiles (d = wn .. wn+63)
            uint32_t bf[4][4];
            #pragma unroll
            for (int nj = 0; nj < 4; nj++)
                ldsm_x4_t(bf[nj],
                          ks_base + ((k0 + b_row) * ASTR + b_col + 16 * nj) * 2);
            #pragma unroll
            for (int mi = 0; mi < 2; mi++)
                #pragma unroll
                for (int ni = 0; ni < 8; ni++)
                    mma16816(acc[mi][ni], af[mi], &bf[ni >> 1][(ni & 1) * 2]);
        }
        __syncthreads();
    }

    // epilogue: fp32 partials
    float* gp = g_kvp + ((size_t)blockIdx.x * BH + bh) * D_DIM * D_DIM;
    #pragma unroll
    for (int mi = 0; mi < 2; mi++) {
        #pragma unroll
        for (int ni = 0; ni < 8; ni++) {
            int r = wm + mi * 16 + g;
            int c = wn + ni * 8 + q2;
            *(float2*)&gp[r * D_DIM + c] =
                make_float2(acc[mi][ni][0], acc[mi][ni][1]);
            *(float2*)&gp[(r + 8) * D_DIM + c] =
                make_float2(acc[mi][ni][2], acc[mi][ni][3]);
        }
    }
}

// ============================================================================
// Kernel 2: reduce SPLIT partials -> fp16 KV^T. grid=1024, block=256.
// ============================================================================
__global__ __launch_bounds__(256) void kv_reduce_h() {
    const int idx = blockIdx.x * 256 + threadIdx.x;     // float4 index (262144)
    const float4* p4 = (const float4*)g_kvp;
    float4 s = p4[idx];
    #pragma unroll
    for (int p = 1; p < SPLIT; p++) {
        float4 v = p4[(size_t)p * (BH * D_DIM * D_DIM / 4) + idx];
        s.x += v.x; s.y += v.y; s.z += v.z; s.w += v.w;
    }
    __half2 h0 = __floats2half2_rn(s.x, s.y);
    __half2 h1 = __floats2half2_rn(s.z, s.w);
    uint2 u;
    u.x = *reinterpret_cast<unsigned int*>(&h0);
    u.y = *reinterpret_cast<unsigned int*>(&h1);
    ((uint2*)g_kvh4)[idx] = u;
}

// ============================================================================
// Kernel 3: out = Q @ KV via HMMA (unchanged from R3 — validated).
// grid = (32 t-tiles, 64 bh), block = 256 (8 warps: 4m x 2n).
// ============================================================================
__global__ __launch_bounds__(256, 2) void out_hmma(const float* __restrict__ Q,
                                                   float* __restrict__ out) {
    extern __shared__ __half sm[];
    __half* Qs = sm;                 // [128][PAD]
    __half* Ws = sm + 128 * PAD;     // [128][PAD]

    const int tid = threadIdx.x;
    const int bh = blockIdx.y;
    const int t0 = blockIdx.x * 128;

    {
        const float4* Qg4 = (const float4*)(Q + ((size_t)bh * T_LEN + t0) * D_DIM);
        #pragma unroll
        for (int u = 0; u < 8; u++) {
            int idx = tid + 256 * u;
            int row = idx >> 4;
            int c8  = idx & 15;
            float4 fa = Qg4[row * 32 + c8 * 2];
            float4 fb = Qg4[row * 32 + c8 * 2 + 1];
            uint2 lo = cvt4h(fa), hi = cvt4h(fb);
            uint4 pk = make_uint4(lo.x, lo.y, hi.x, hi.y);
            *(uint4*)&Qs[row * PAD + c8 * 8] = pk;
        }
    }
    {
        const uint4* Bg = g_kvh4 + (size_t)bh * 2048;
        #pragma unroll
        for (int u = 0; u < 8; u++) {
            int idx = tid + 256 * u;
            int row = idx >> 4;
            int c8  = idx & 15;
            *(uint4*)&Ws[row * PAD + c8 * 8] = Bg[row * 16 + c8];
        }
    }
    __syncthreads();

    const int wid = tid >> 5;
    const int l   = tid & 31;
    const int g   = l >> 2;
    const int q2  = (l & 3) * 2;
    const int wm  = (wid & 3) * 32;
    const int wn  = (wid >> 2) * 64;

    float acc[2][8][4];
    #pragma unroll
    for (int i = 0; i < 2; i++)
        #pragma unroll
        for (int j = 0; j < 8; j++)
            #pragma unroll
            for (int v = 0; v < 4; v++) acc[i][j][v] = 0.f;

    #pragma unroll
    for (int k0 = 0; k0 < 128; k0 += 16) {
        uint32_t af[2][4];
        #pragma unroll
        for (int mi = 0; mi < 2; mi++) {
            int r = wm + mi * 16 + g;
            af[mi][0] = *(const uint32_t*)&Qs[r * PAD + k0 + q2];
            af[mi][1] = *(const uint32_t*)&Qs[(r + 8) * PAD + k0 + q2];
            af[mi][2] = *(const uint32_t*)&Qs[r * PAD + k0 + q2 + 8];
            af[mi][3] = *(const uint32_t*)&Qs[(r + 8) * PAD + k0 + q2 + 8];
        }
        #pragma unroll
        for (int ni = 0; ni < 8; ni++) {
            int e = wn + ni * 8 + g;
            uint32_t bf[2];
            bf[0] = *(const uint32_t*)&Ws[e * PAD + k0 + q2];
            bf[1] = *(const uint32_t*)&Ws[e * PAD + k0 + q2 + 8];
            mma16816(acc[0][ni], af[0], bf);
            mma16816(acc[1][ni], af[1], bf);
        }
    }

    float* Ob = out + ((size_t)bh * T_LEN + t0) * D_DIM;
    #pragma unroll
    for (int mi = 0; mi < 2; mi++) {
        #pragma unroll
        for (int ni = 0; ni < 8; ni++) {
            int r = wm + mi * 16 + g;
            int c = wn + ni * 8 + q2;
            *(float2*)&Ob[(size_t)r * D_DIM + c] =
                make_float2(acc[mi][ni][0], acc[mi][ni][1]);
            *(float2*)&Ob[(size_t)(r + 8) * D_DIM + c] =
                make_float2(acc[mi][ni][2], acc[mi][ni][3]);
        }
    }
}

// ============================================================================
extern "C" void kernel_launch(void* const* d_in, const int* in_sizes, int n_in,
                              void* d_out, int out_size) {
    const float* Q = (const float*)d_in[0];
    const float* K = (const float*)d_in[1];
    const float* V = (const float*)d_in[2];
    float* out = (float*)d_out;

    kv_hmma<<<dim3(SPLIT, BH), 256>>>(K, V);
    kv_reduce_h<<<1024, 256>>>();

    const int smem = 2 * 128 * PAD * sizeof(__half);   // 69632 B
    cudaFuncSetAttribute(out_hmma,
                         cudaFuncAttributeMaxDynamicSharedMemorySize, smem);
    out_hmma<<<dim3(T_LEN / 128, BH), 256, smem>>>(Q, out);
}